// round 9
// baseline (speedup 1.0000x reference)
#include <cuda_runtime.h>
#include <cuda_bf16.h>

#define LNUM 2
#define BB 64
#define TSTEPS 512
#define DIN 512
#define HD 512
#define PD 256
#define OD 512
#define NBLK 148
#define NTHR 256

// ----------------- persistent device state (no allocations) -----------------
__device__ float g_h[LNUM][BB * HD];   // h_mem per layer
__device__ float g_m[LNUM][BB * PD];   // memory per layer
__device__ float g_rh[BB * HD];        // sigma(r) * h_old
__device__ float g_us[BB * HD];        // sigma(u)
__device__ float g_hc[BB * HD];        // h_cand
__device__ float g_mo[BB * PD];        // read_gate * m
__device__ float g_wg[4][BB * PD];     // write-gate preacts (bias included)
__device__ unsigned g_count;
__device__ unsigned g_gen;

struct Params {
    const float *x, *Wr, *br, *Wu, *bu, *Wn, *bn, *Wmr, *bmr, *Wmw, *bmw,
                *Wmu, *bmu, *Wmh, *bmh, *Wd, *bd, *Ws, *bs, *Wout, *bout,
                *dop, *ser;
    float* out;
    long long out_size;
};

__device__ __forceinline__ float sigf(float v) { return 1.f / (1.f + __expf(-v)); }
__device__ __forceinline__ float tanhf_(float v) {
    float e = __expf(-2.f * fabsf(v));
    float r = (1.f - e) / (1.f + e);
    return v < 0.f ? -r : r;
}

__device__ __forceinline__ void gridbar() {
    __syncthreads();
    if (threadIdx.x == 0) {
        __threadfence();
        unsigned gen = *(volatile unsigned*)&g_gen;
        unsigned a = atomicAdd(&g_count, 1u);
        if (a == NBLK - 1) {
            atomicExch(&g_count, 0u);
            __threadfence();
            atomicAdd(&g_gen, 1u);
        } else {
            while (*(volatile unsigned*)&g_gen == gen) __nanosleep(64);
        }
        __threadfence();
    }
    __syncthreads();
}

struct alignas(16) SM {
    float A[2][32 * 65];  // [k][row], stride 65 -> conflict-free
    float W[2][32 * 36];  // [k][col], stride 36 -> aligned float4 reads
};

// C[64, 32] = A[64, Ktot] * W[32, Ktot]^T, Wp pre-offset to its 32-row block.
// A = concat(A1 rows for k<K1, A2 for k>=K1); 32-chunks never straddle K1.
// Thread map: row = tid&63, colgroup = tid>>6 (8 cols/thread).
__device__ __forceinline__ void gemm_tile(
    SM& sm,
    const float* __restrict__ A1, long lda1, int K1,
    const float* __restrict__ A2, int lda2, int Ktot,
    const float* __restrict__ Wp, int wstr, float accf[8])
{
    const int tid = threadIdx.x;
    const int kq = tid & 31;
    const int rq = tid >> 5;       // 0..7
    const int row = tid & 63;
    const int cg = tid >> 6;       // 0..3
    const int nch = Ktot >> 5;
    float ra[8], rw[4];
#pragma unroll
    for (int j = 0; j < 8; j++) accf[j] = 0.f;

    // prologue: load chunk 0 (always from A1 since K1 >= 32)
    {
#pragma unroll
        for (int i = 0; i < 8; i++)
            ra[i] = A1[(long)(rq + 8 * i) * lda1 + kq];
#pragma unroll
        for (int i = 0; i < 4; i++)
            rw[i] = Wp[(size_t)(rq + 8 * i) * wstr + kq];
    }
#pragma unroll
    for (int i = 0; i < 8; i++) sm.A[0][kq * 65 + rq + 8 * i] = ra[i];
#pragma unroll
    for (int i = 0; i < 4; i++) sm.W[0][kq * 36 + rq + 8 * i] = rw[i];

#pragma unroll 1
    for (int ch = 0; ch < nch; ch++) {
        __syncthreads();
        const bool more = (ch + 1 < nch);
        if (more) {
            int kb = ((ch + 1) << 5) + kq;
            if (kb < K1) {
#pragma unroll
                for (int i = 0; i < 8; i++)
                    ra[i] = A1[(long)(rq + 8 * i) * lda1 + kb];
            } else {
                int ko = kb - K1;
#pragma unroll
                for (int i = 0; i < 8; i++)
                    ra[i] = A2[(rq + 8 * i) * lda2 + ko];
            }
#pragma unroll
            for (int i = 0; i < 4; i++)
                rw[i] = Wp[(size_t)(rq + 8 * i) * wstr + kb];
        }
        const int b = ch & 1;
        const float* as = &sm.A[b][row];
        const float* ws = &sm.W[b][cg * 8];
#pragma unroll
        for (int k = 0; k < 32; k++) {
            float a = as[k * 65];
            float4 w0 = *(const float4*)(ws + k * 36);
            float4 w1 = *(const float4*)(ws + k * 36 + 4);
            accf[0] = fmaf(a, w0.x, accf[0]);
            accf[1] = fmaf(a, w0.y, accf[1]);
            accf[2] = fmaf(a, w0.z, accf[2]);
            accf[3] = fmaf(a, w0.w, accf[3]);
            accf[4] = fmaf(a, w1.x, accf[4]);
            accf[5] = fmaf(a, w1.y, accf[5]);
            accf[6] = fmaf(a, w1.z, accf[6]);
            accf[7] = fmaf(a, w1.w, accf[7]);
        }
        if (more) {
            const int nb = (ch + 1) & 1;
#pragma unroll
            for (int i = 0; i < 8; i++) sm.A[nb][kq * 65 + rq + 8 * i] = ra[i];
#pragma unroll
            for (int i = 0; i < 4; i++) sm.W[nb][kq * 36 + rq + 8 * i] = rw[i];
        }
    }
    __syncthreads();
}

__device__ __forceinline__ const float* wgW(const Params& pr, int g) {
    return (g == 0) ? pr.Wmw : (g == 1) ? pr.Wmu : (g == 2) ? pr.Wd : pr.Ws;
}
__device__ __forceinline__ const float* wgB(const Params& pr, int g) {
    return (g == 0) ? pr.bmw : (g == 1) ? pr.bmu : (g == 2) ? pr.bd : pr.bs;
}

// memory update for layer l from g_wg preacts (bias already included)
__device__ __forceinline__ void ec_m(int l, int e, float dopa, float sero) {
    const int tid = threadIdx.x;
#pragma unroll
    for (int j = 0; j < 8; j++) {
        int i = e * 2048 + j * 256 + tid;
        float w = sigf(g_wg[0][i]) * sigf(g_wg[2][i] * dopa)
                  * (1.f - sigf(g_wg[3][i] * sero));
        g_m[l][i] = (1.f - w) * g_m[l][i] + w * tanhf_(g_wg[1][i]);
    }
}

__global__ void __launch_bounds__(NTHR, 1)
gru_kernel(Params pr)
{
    __shared__ SM sm;
    const int tid = threadIdx.x;
    const int row = tid & 63;
    const int cg = tid >> 6;
    const float dopa = pr.dop[0];
    const float sero = pr.ser[0];

    for (int i = blockIdx.x * NTHR + tid; i < LNUM * BB * HD; i += NBLK * NTHR)
        (&g_h[0][0])[i] = 0.f;
    for (int i = blockIdx.x * NTHR + tid; i < LNUM * BB * PD; i += NBLK * NTHR)
        (&g_m[0][0])[i] = 0.f;
    gridbar();

    for (int t = 0; t < TSTEPS; t++) {
        const float* xt = pr.x + (size_t)t * DIN;
        float accf[8];

        // ---- P1: r0, u0 (full-K) + out(t-1) + layer-1 write gates(t-1) ----
        {
            int nt = t ? 80 : 32;
            for (int tile = blockIdx.x; tile < nt; tile += NBLK) {
                if (tile < 16) {  // r0: K=1024, A=[x|h0]
                    int c0 = tile * 32;
                    gemm_tile(sm, xt, (long)TSTEPS * DIN, DIN, g_h[0], HD,
                              DIN + HD, pr.Wr + (size_t)c0 * (DIN + HD),
                              DIN + HD, accf);
#pragma unroll
                    for (int j = 0; j < 8; j++) {
                        int c = c0 + cg * 8 + j;
                        int idx = row * HD + c;
                        g_rh[idx] = sigf(accf[j] + pr.br[c]) * g_h[0][idx];
                    }
                } else if (tile < 32) {  // u0
                    int c0 = (tile - 16) * 32;
                    gemm_tile(sm, xt, (long)TSTEPS * DIN, DIN, g_h[0], HD,
                              DIN + HD, pr.Wu + (size_t)c0 * (DIN + HD),
                              DIN + HD, accf);
#pragma unroll
                    for (int j = 0; j < 8; j++) {
                        int c = c0 + cg * 8 + j;
                        g_us[row * HD + c] = sigf(accf[j] + pr.bu[c]);
                    }
                } else if (tile < 48) {  // out(t-1): K=512, A=h1
                    int c0 = (tile - 32) * 32;
                    gemm_tile(sm, g_h[1], HD, HD, g_h[1], HD, HD,
                              pr.Wout + (size_t)c0 * HD, HD, accf);
#pragma unroll
                    for (int j = 0; j < 8; j++) {
                        int c = c0 + cg * 8 + j;
                        pr.out[((size_t)row * TSTEPS + (t - 1)) * OD + c] =
                            accf[j] + pr.bout[c];
                    }
                } else {  // layer-1 write gates(t-1): K=512, A=h1
                    int q = tile - 48;
                    int gi = q >> 3;
                    int c0 = (q & 7) * 32;
                    gemm_tile(sm, g_h[1], HD, HD, g_h[1], HD, HD,
                              wgW(pr, gi) + (size_t)(PD + c0) * HD, HD, accf);
                    const float* bg = wgB(pr, gi);
#pragma unroll
                    for (int j = 0; j < 8; j++) {
                        int c = c0 + cg * 8 + j;
                        g_wg[gi][row * PD + c] = accf[j] + bg[PD + c];
                    }
                }
            }
        }
        gridbar();

        // ---- P2: n0 (A=[x|rh]) + m1-combine(t-1) ----
        {
            int nt = t ? 24 : 16;
            for (int tile = blockIdx.x; tile < nt; tile += NBLK) {
                if (tile < 16) {
                    int c0 = tile * 32;
                    gemm_tile(sm, xt, (long)TSTEPS * DIN, DIN, g_rh, HD,
                              DIN + HD, pr.Wn + (size_t)c0 * (DIN + HD),
                              DIN + HD, accf);
#pragma unroll
                    for (int j = 0; j < 8; j++) {
                        int c = c0 + cg * 8 + j;
                        int idx = row * HD + c;
                        float nh = tanhf_(accf[j] + pr.bn[c]);
                        float u = g_us[idx];
                        g_hc[idx] = (1.f - u) * g_h[0][idx] + u * nh;
                    }
                } else {
                    ec_m(1, tile - 16, dopa, sero);
                }
            }
        }
        gridbar();

        // ---- P3: read-gate0: K=512, A=g_hc ----
        for (int tile = blockIdx.x; tile < 8; tile += NBLK) {
            int c0 = tile * 32;
            gemm_tile(sm, g_hc, HD, HD, g_hc, HD, HD,
                      pr.Wmr + (size_t)c0 * HD, HD, accf);
#pragma unroll
            for (int j = 0; j < 8; j++) {
                int c = c0 + cg * 8 + j;
                int idx = row * PD + c;
                g_mo[idx] = sigf(accf[j] + pr.bmr[c]) * g_m[0][idx];
            }
        }
        gridbar();

        // ---- P4: h_mem0 = hc + mo*Wmh^T + bmh: K=256 ----
        for (int tile = blockIdx.x; tile < 16; tile += NBLK) {
            int c0 = tile * 32;
            gemm_tile(sm, g_mo, PD, PD, g_mo, PD, PD,
                      pr.Wmh + (size_t)c0 * PD, PD, accf);
#pragma unroll
            for (int j = 0; j < 8; j++) {
                int c = c0 + cg * 8 + j;
                int idx = row * HD + c;
                g_h[0][idx] = g_hc[idx] + accf[j] + pr.bmh[c];
            }
        }
        gridbar();

        // ---- P5: r1, u1 (A=[h0|h1]) + layer-0 write gates (A=h0) ----
        for (int tile = blockIdx.x; tile < 64; tile += NBLK) {
            if (tile < 16) {  // r1
                int c0 = tile * 32;
                gemm_tile(sm, g_h[0], HD, HD, g_h[1], HD, DIN + HD,
                          pr.Wr + (size_t)(HD + c0) * (DIN + HD),
                          DIN + HD, accf);
#pragma unroll
                for (int j = 0; j < 8; j++) {
                    int c = c0 + cg * 8 + j;
                    int idx = row * HD + c;
                    g_rh[idx] = sigf(accf[j] + pr.br[HD + c]) * g_h[1][idx];
                }
            } else if (tile < 32) {  // u1
                int c0 = (tile - 16) * 32;
                gemm_tile(sm, g_h[0], HD, HD, g_h[1], HD, DIN + HD,
                          pr.Wu + (size_t)(HD + c0) * (DIN + HD),
                          DIN + HD, accf);
#pragma unroll
                for (int j = 0; j < 8; j++) {
                    int c = c0 + cg * 8 + j;
                    g_us[row * HD + c] = sigf(accf[j] + pr.bu[HD + c]);
                }
            } else {  // layer-0 write gates: K=512, A=h0(new)
                int q = tile - 32;
                int gi = q >> 3;
                int c0 = (q & 7) * 32;
                gemm_tile(sm, g_h[0], HD, HD, g_h[0], HD, HD,
                          wgW(pr, gi) + (size_t)c0 * HD, HD, accf);
                const float* bg = wgB(pr, gi);
#pragma unroll
                for (int j = 0; j < 8; j++) {
                    int c = c0 + cg * 8 + j;
                    g_wg[gi][row * PD + c] = accf[j] + bg[c];
                }
            }
        }
        gridbar();

        // ---- P6: n1 (A=[h0|rh]) + m0-combine ----
        for (int tile = blockIdx.x; tile < 24; tile += NBLK) {
            if (tile < 16) {
                int c0 = tile * 32;
                gemm_tile(sm, g_h[0], HD, HD, g_rh, HD, DIN + HD,
                          pr.Wn + (size_t)(HD + c0) * (DIN + HD),
                          DIN + HD, accf);
#pragma unroll
                for (int j = 0; j < 8; j++) {
                    int c = c0 + cg * 8 + j;
                    int idx = row * HD + c;
                    float nh = tanhf_(accf[j] + pr.bn[HD + c]);
                    float u = g_us[idx];
                    g_hc[idx] = (1.f - u) * g_h[1][idx] + u * nh;
                }
            } else {
                ec_m(0, tile - 16, dopa, sero);
            }
        }
        gridbar();

        // ---- P7: read-gate1 ----
        for (int tile = blockIdx.x; tile < 8; tile += NBLK) {
            int c0 = tile * 32;
            gemm_tile(sm, g_hc, HD, HD, g_hc, HD, HD,
                      pr.Wmr + (size_t)(PD + c0) * HD, HD, accf);
#pragma unroll
            for (int j = 0; j < 8; j++) {
                int c = c0 + cg * 8 + j;
                int idx = row * PD + c;
                g_mo[idx] = sigf(accf[j] + pr.bmr[PD + c]) * g_m[1][idx];
            }
        }
        gridbar();

        // ---- P8: h_mem1 ----
        for (int tile = blockIdx.x; tile < 16; tile += NBLK) {
            int c0 = tile * 32;
            gemm_tile(sm, g_mo, PD, PD, g_mo, PD, PD,
                      pr.Wmh + (size_t)(HD + c0) * PD, PD, accf);
#pragma unroll
            for (int j = 0; j < 8; j++) {
                int c = c0 + cg * 8 + j;
                int idx = row * HD + c;
                g_h[1][idx] = g_hc[idx] + accf[j] + pr.bmh[HD + c];
            }
        }
        gridbar();
    }

    // ---- PF1: out(T-1) + layer-1 write gates of last step ----
    {
        float accf[8];
        for (int tile = blockIdx.x; tile < 48; tile += NBLK) {
            if (tile < 16) {
                int c0 = tile * 32;
                gemm_tile(sm, g_h[1], HD, HD, g_h[1], HD, HD,
                          pr.Wout + (size_t)c0 * HD, HD, accf);
#pragma unroll
                for (int j = 0; j < 8; j++) {
                    int c = c0 + cg * 8 + j;
                    pr.out[((size_t)row * TSTEPS + (TSTEPS - 1)) * OD + c] =
                        accf[j] + pr.bout[c];
                }
            } else {
                int q = tile - 16;
                int gi = q >> 3;
                int c0 = (q & 7) * 32;
                gemm_tile(sm, g_h[1], HD, HD, g_h[1], HD, HD,
                          wgW(pr, gi) + (size_t)(PD + c0) * HD, HD, accf);
                const float* bg = wgB(pr, gi);
#pragma unroll
                for (int j = 0; j < 8; j++) {
                    int c = c0 + cg * 8 + j;
                    g_wg[gi][row * PD + c] = accf[j] + bg[PD + c];
                }
            }
        }
    }
    gridbar();

    // ---- PF2: final m1-combine ----
    for (int tile = blockIdx.x; tile < 8; tile += NBLK)
        ec_m(1, tile, dopa, sero);
    gridbar();

    // ---- PF3: h_final, m_final (guarded by out_size) ----
    {
        long long base_h = (long long)BB * TSTEPS * OD;
        long long base_m = base_h + (long long)LNUM * BB * HD;
        const float* hp = &g_h[0][0];
        for (int i = blockIdx.x * NTHR + tid; i < LNUM * BB * HD; i += NBLK * NTHR)
            if (base_h + i < pr.out_size) pr.out[base_h + i] = hp[i];
        const float* mp = &g_m[0][0];
        for (int i = blockIdx.x * NTHR + tid; i < LNUM * BB * PD; i += NBLK * NTHR)
            if (base_m + i < pr.out_size) pr.out[base_m + i] = mp[i];
    }
}

extern "C" void kernel_launch(void* const* d_in, const int* in_sizes, int n_in,
                              void* d_out, int out_size) {
    Params p;
    p.x    = (const float*)d_in[0];
    p.Wr   = (const float*)d_in[1];
    p.br   = (const float*)d_in[2];
    p.Wu   = (const float*)d_in[3];
    p.bu   = (const float*)d_in[4];
    p.Wn   = (const float*)d_in[5];
    p.bn   = (const float*)d_in[6];
    p.Wmr  = (const float*)d_in[7];
    p.bmr  = (const float*)d_in[8];
    p.Wmw  = (const float*)d_in[9];
    p.bmw  = (const float*)d_in[10];
    p.Wmu  = (const float*)d_in[11];
    p.bmu  = (const float*)d_in[12];
    p.Wmh  = (const float*)d_in[13];
    p.bmh  = (const float*)d_in[14];
    p.Wd   = (const float*)d_in[15];
    p.bd   = (const float*)d_in[16];
    p.Ws   = (const float*)d_in[17];
    p.bs   = (const float*)d_in[18];
    p.Wout = (const float*)d_in[19];
    p.bout = (const float*)d_in[20];
    p.dop  = (const float*)d_in[21];
    p.ser  = (const float*)d_in[22];
    p.out  = (float*)d_out;
    p.out_size = (long long)out_size;
    gru_kernel<<<NBLK, NTHR>>>(p);
}

// round 10
// speedup vs baseline: 1.4518x; 1.4518x over previous
#include <cuda_runtime.h>
#include <cuda_bf16.h>

#define LNUM 2
#define BB 64
#define TSTEPS 512
#define DIN 512
#define HD 512
#define PD 256
#define OD 512
#define NBLK 148
#define NTHR 256

// ----------------- persistent device state (no allocations) -----------------
__device__ float g_h[LNUM][BB * HD];    // h_mem per layer
__device__ float g_m[LNUM][BB * PD];    // memory per layer
__device__ float g_rh[BB * HD];         // sigma(r) * h_old   (current layer)
__device__ float g_us[BB * HD];         // sigma(u)           (current layer)
__device__ float g_hc[BB * HD];         // h_cand             (current layer)
__device__ float g_mo[BB * PD];         // read_gate * m      (current layer)
__device__ float g_pr[4][BB * HD];      // r preact partials (split-4)
__device__ float g_pu[4][BB * HD];      // u preact partials (split-4)
__device__ float g_pn[4][BB * HD];      // n preact partials (2 x-half + 2 rh-half)
__device__ float g_pwg[4][2][BB * PD];  // write-gate raw partials: mw,mu,d,s x split-2
__device__ float g_po[2][BB * OD];      // output raw partials (split-2)
__device__ unsigned g_count;
__device__ unsigned g_gen;

struct Params {
    const float *x, *Wr, *br, *Wu, *bu, *Wn, *bn, *Wmr, *bmr, *Wmw, *bmw,
                *Wmu, *bmu, *Wmh, *bmh, *Wd, *bd, *Ws, *bs, *Wout, *bout,
                *dop, *ser;
    float* out;
    long long out_size;
};

__device__ __forceinline__ float sigf(float v) { return 1.f / (1.f + __expf(-v)); }
__device__ __forceinline__ float tanhf_(float v) {
    float e = __expf(-2.f * fabsf(v));
    float r = (1.f - e) / (1.f + e);
    return v < 0.f ? -r : r;
}

__device__ __forceinline__ void gridbar() {
    __syncthreads();
    if (threadIdx.x == 0) {
        __threadfence();
        unsigned gen = *(volatile unsigned*)&g_gen;
        unsigned a = atomicAdd(&g_count, 1u);
        if (a == NBLK - 1) {
            atomicExch(&g_count, 0u);
            __threadfence();
            atomicAdd(&g_gen, 1u);
        } else {
            while (*(volatile unsigned*)&g_gen == gen) __nanosleep(64);
        }
        __threadfence();
    }
    __syncthreads();
}

struct alignas(16) SM {
    float A[2][32 * 65];  // [k][row], stride 65 -> conflict-free
    float W[2][32 * 36];  // [k][col], stride 36 -> aligned float4 reads
};

// C[64, 32] += A[64, 32*nch] * W[32, 32*nch]^T.
// A pre-offset to its k-window (single plain array); Wp pre-offset to (c0, k0).
// Thread map: row = tid&63, colgroup = tid>>6 (8 cols/thread).
__device__ __forceinline__ void gemm_tile(
    SM& sm, const float* __restrict__ A, long lda,
    const float* __restrict__ Wp, int wstr, int nch, float accf[8])
{
    const int tid = threadIdx.x;
    const int kq = tid & 31;
    const int rq = tid >> 5;   // 0..7
    const int row = tid & 63;
    const int cg = tid >> 6;   // 0..3
    float ra[8], rw[4];
#pragma unroll
    for (int j = 0; j < 8; j++) accf[j] = 0.f;

    // prologue: chunk 0
#pragma unroll
    for (int i = 0; i < 8; i++) ra[i] = A[(long)(rq + 8 * i) * lda + kq];
#pragma unroll
    for (int i = 0; i < 4; i++) rw[i] = Wp[(size_t)(rq + 8 * i) * wstr + kq];
#pragma unroll
    for (int i = 0; i < 8; i++) sm.A[0][kq * 65 + rq + 8 * i] = ra[i];
#pragma unroll
    for (int i = 0; i < 4; i++) sm.W[0][kq * 36 + rq + 8 * i] = rw[i];

#pragma unroll 1
    for (int ch = 0; ch < nch; ch++) {
        __syncthreads();
        const bool more = (ch + 1 < nch);
        if (more) {
            int kb = ((ch + 1) << 5) + kq;
#pragma unroll
            for (int i = 0; i < 8; i++) ra[i] = A[(long)(rq + 8 * i) * lda + kb];
#pragma unroll
            for (int i = 0; i < 4; i++) rw[i] = Wp[(size_t)(rq + 8 * i) * wstr + kb];
        }
        const int b = ch & 1;
        const float* as = &sm.A[b][row];
        const float* ws = &sm.W[b][cg * 8];
#pragma unroll
        for (int k = 0; k < 32; k++) {
            float a = as[k * 65];
            float4 w0 = *(const float4*)(ws + k * 36);
            float4 w1 = *(const float4*)(ws + k * 36 + 4);
            accf[0] = fmaf(a, w0.x, accf[0]);
            accf[1] = fmaf(a, w0.y, accf[1]);
            accf[2] = fmaf(a, w0.z, accf[2]);
            accf[3] = fmaf(a, w0.w, accf[3]);
            accf[4] = fmaf(a, w1.x, accf[4]);
            accf[5] = fmaf(a, w1.y, accf[5]);
            accf[6] = fmaf(a, w1.z, accf[6]);
            accf[7] = fmaf(a, w1.w, accf[7]);
        }
        if (more) {
            const int nb = (ch + 1) & 1;
#pragma unroll
            for (int i = 0; i < 8; i++) sm.A[nb][kq * 65 + rq + 8 * i] = ra[i];
#pragma unroll
            for (int i = 0; i < 4; i++) sm.W[nb][kq * 36 + rq + 8 * i] = rw[i];
        }
    }
    __syncthreads();
}

__device__ __forceinline__ void store_part(float* __restrict__ part, int N,
                                           int c0, const float* accf) {
    const int row = threadIdx.x & 63, cg = threadIdx.x >> 6;
    float4* p = (float4*)(part + (size_t)row * N + c0 + cg * 8);
    p[0] = make_float4(accf[0], accf[1], accf[2], accf[3]);
    p[1] = make_float4(accf[4], accf[5], accf[6], accf[7]);
}

__device__ __forceinline__ const float* wgW(const Params& pr, int g) {
    return (g == 0) ? pr.Wmw : (g == 1) ? pr.Wmu : (g == 2) ? pr.Wd : pr.Ws;
}

// elementwise: materialize sigma(r)*h and sigma(u) from split-4 partials
__device__ __forceinline__ void ew_ru(int l, int e, const Params& pr) {
    const int tid = threadIdx.x;
#pragma unroll
    for (int j = 0; j < 8; j++) {
        int i = e * 2048 + j * 256 + tid;
        int c = i & 511;
        float rr = g_pr[0][i] + g_pr[1][i] + g_pr[2][i] + g_pr[3][i]
                   + pr.br[l * HD + c];
        g_rh[i] = sigf(rr) * g_h[l][i];
        float uu = g_pu[0][i] + g_pu[1][i] + g_pu[2][i] + g_pu[3][i]
                   + pr.bu[l * HD + c];
        g_us[i] = sigf(uu);
    }
}

// elementwise: materialize h_cand from n partials + sigma(u)
__device__ __forceinline__ void ew_hc(int l, int e, const Params& pr) {
    const int tid = threadIdx.x;
#pragma unroll
    for (int j = 0; j < 8; j++) {
        int i = e * 2048 + j * 256 + tid;
        int c = i & 511;
        float nn = g_pn[0][i] + g_pn[1][i] + g_pn[2][i] + g_pn[3][i]
                   + pr.bn[l * HD + c];
        float u = g_us[i];
        g_hc[i] = (1.f - u) * g_h[l][i] + u * tanhf_(nn);
    }
}

// elementwise: apply memory update for layer l from raw write-gate partials
__device__ __forceinline__ void ec_m(int l, int e, const Params& pr,
                                     float dopa, float sero) {
    const int tid = threadIdx.x;
#pragma unroll
    for (int j = 0; j < 8; j++) {
        int i = e * 2048 + j * 256 + tid;
        int c = i & 255;
        float wmw = g_pwg[0][0][i] + g_pwg[0][1][i] + pr.bmw[l * PD + c];
        float wmu = g_pwg[1][0][i] + g_pwg[1][1][i] + pr.bmu[l * PD + c];
        float wd  = g_pwg[2][0][i] + g_pwg[2][1][i] + pr.bd[l * PD + c];
        float wsv = g_pwg[3][0][i] + g_pwg[3][1][i] + pr.bs[l * PD + c];
        float w = sigf(wmw) * sigf(wd * dopa) * (1.f - sigf(wsv * sero));
        g_m[l][i] = (1.f - w) * g_m[l][i] + w * tanhf_(wmu);
    }
}

__device__ __forceinline__ void ec_out(int tprev, int e, const Params& pr) {
    const int tid = threadIdx.x;
#pragma unroll
    for (int j = 0; j < 8; j++) {
        int i = e * 2048 + j * 256 + tid;
        int r = i >> 9, c = i & 511;
        pr.out[((size_t)r * TSTEPS + tprev) * OD + c] =
            g_po[0][i] + g_po[1][i] + pr.bout[c];
    }
}

__global__ void __launch_bounds__(NTHR, 1)
gru_kernel(Params pr)
{
    __shared__ SM sm;
    const int tid = threadIdx.x;
    const int row = tid & 63;
    const int cg = tid >> 6;
    const float dopa = pr.dop[0];
    const float sero = pr.ser[0];

    for (int i = blockIdx.x * NTHR + tid; i < LNUM * BB * HD; i += NBLK * NTHR)
        (&g_h[0][0])[i] = 0.f;
    for (int i = blockIdx.x * NTHR + tid; i < LNUM * BB * PD; i += NBLK * NTHR)
        (&g_m[0][0])[i] = 0.f;
    gridbar();

    const long LDX = (long)TSTEPS * DIN;  // batch-row stride of x

    for (int t = 0; t < TSTEPS; t++) {
        const float* xt = pr.x + (size_t)t * DIN;
        float acc[8];

        for (int l = 0; l < LNUM; l++) {
            // ---- A: r,u split-4 (128 tiles, 8 chunks each) ----
            for (int tile = blockIdx.x; tile < 128; tile += NBLK) {
                int which = tile >> 6, q = tile & 63;
                int c0 = (q >> 2) * 32, s = q & 3, k0 = s * 256;
                const float* A; long lda;
                if (l == 0) {
                    if (s < 2) { A = xt + k0; lda = LDX; }
                    else       { A = g_h[0] + (k0 - 512); lda = HD; }
                } else {
                    if (s < 2) { A = g_h[0] + k0; lda = HD; }
                    else       { A = g_h[1] + (k0 - 512); lda = HD; }
                }
                const float* W = (which ? pr.Wu : pr.Wr)
                                 + (size_t)(l * HD + c0) * (DIN + HD) + k0;
                gemm_tile(sm, A, lda, W, DIN + HD, 8, acc);
                store_part((which ? g_pu : g_pr)[s], HD, c0, acc);
            }
            gridbar();

            // ---- B: ew_ru (16) + n-firsthalf split-2 (32)
            //         + [l==0,t>0: out(t-1) split-2 (32)]
            //         + [wg of other layer, split-2 (64)] ----
            {
                int ntB = (l == 0) ? (t ? 144 : 48) : 112;
                int wgbase = (l == 0) ? 80 : 48;
                for (int tile = blockIdx.x; tile < ntB; tile += NBLK) {
                    if (tile < 16) {
                        ew_ru(l, tile, pr);
                    } else if (tile < 48) {  // n first half (x-part / h0-part)
                        int q = tile - 16;
                        int c0 = (q >> 1) * 32, s = q & 1, k0 = s * 256;
                        const float* A; long lda;
                        if (l == 0) { A = xt + k0; lda = LDX; }
                        else        { A = g_h[0] + k0; lda = HD; }
                        const float* W = pr.Wn
                            + (size_t)(l * HD + c0) * (DIN + HD) + k0;
                        gemm_tile(sm, A, lda, W, DIN + HD, 8, acc);
                        store_part(g_pn[s], HD, c0, acc);
                    } else if (l == 0 && tile < 80) {  // out(t-1) from h1(t-1)
                        int q = tile - 48;
                        int c0 = (q >> 1) * 32, s = q & 1;
                        gemm_tile(sm, g_h[1] + s * 256, HD,
                                  pr.Wout + (size_t)c0 * HD + s * 256, HD, 8,
                                  acc);
                        store_part(g_po[s], OD, c0, acc);
                    } else {  // write gates of layer lw
                        int lw = 1 - l;  // l==0: layer-1 gates (t-1); l==1: layer-0 gates (t)
                        int q = tile - wgbase, g = q >> 4, r2 = q & 15;
                        int c0 = (r2 >> 1) * 32, s = r2 & 1;
                        gemm_tile(sm, g_h[lw] + s * 256, HD,
                                  wgW(pr, g) + (size_t)(lw * PD + c0) * HD
                                      + s * 256,
                                  HD, 8, acc);
                        store_part(g_pwg[g][s], PD, c0, acc);
                    }
                }
            }
            gridbar();

            // ---- C: n-secondhalf split-2 (32)
            //         + [l==0,t>0: ec_m(1) (8) + ec_out(t-1) (16)]
            //         + [l==1: ec_m(0) (8)] ----
            {
                int ntC = (l == 0) ? (t ? 56 : 32) : 40;
                for (int tile = blockIdx.x; tile < ntC; tile += NBLK) {
                    if (tile < 32) {
                        int c0 = (tile >> 1) * 32, s = tile & 1, k0 = s * 256;
                        const float* W = pr.Wn
                            + (size_t)(l * HD + c0) * (DIN + HD) + DIN + k0;
                        gemm_tile(sm, g_rh + k0, HD, W, DIN + HD, 8, acc);
                        store_part(g_pn[2 + s], HD, c0, acc);
                    } else if (tile < 40) {
                        ec_m(1 - l, tile - 32, pr, dopa, sero);
                    } else {
                        ec_out(t - 1, tile - 40, pr);
                    }
                }
            }
            gridbar();

            // ---- D: materialize h_cand (16 tiles) ----
            for (int tile = blockIdx.x; tile < 16; tile += NBLK)
                ew_hc(l, tile, pr);
            gridbar();

            // ---- E: read gate, K=512 unsplit (8 tiles, 16 chunks) ----
            for (int tile = blockIdx.x; tile < 8; tile += NBLK) {
                int c0 = tile * 32;
                gemm_tile(sm, g_hc, HD,
                          pr.Wmr + (size_t)(l * PD + c0) * HD, HD, 16, acc);
#pragma unroll
                for (int j = 0; j < 8; j++) {
                    int c = c0 + cg * 8 + j;
                    int idx = row * PD + c;
                    g_mo[idx] = sigf(acc[j] + pr.bmr[l * PD + c]) * g_m[l][idx];
                }
            }
            gridbar();

            // ---- F: h_mem = hc + mo*Wmh^T + bmh, K=256 (16 tiles, 8 chunks) ----
            for (int tile = blockIdx.x; tile < 16; tile += NBLK) {
                int c0 = tile * 32;
                gemm_tile(sm, g_mo, PD,
                          pr.Wmh + (size_t)(l * HD + c0) * PD, PD, 8, acc);
#pragma unroll
                for (int j = 0; j < 8; j++) {
                    int c = c0 + cg * 8 + j;
                    int idx = row * HD + c;
                    g_h[l][idx] = g_hc[idx] + acc[j] + pr.bmh[l * HD + c];
                }
            }
            gridbar();
        }
    }

    // ---- PF1: out(T-1) split-2 (32) + layer-1 write gates split-2 (64) ----
    {
        float acc[8];
        for (int tile = blockIdx.x; tile < 96; tile += NBLK) {
            if (tile < 32) {
                int c0 = (tile >> 1) * 32, s = tile & 1;
                gemm_tile(sm, g_h[1] + s * 256, HD,
                          pr.Wout + (size_t)c0 * HD + s * 256, HD, 8, acc);
                store_part(g_po[s], OD, c0, acc);
            } else {
                int q = tile - 32, g = q >> 4, r2 = q & 15;
                int c0 = (r2 >> 1) * 32, s = r2 & 1;
                gemm_tile(sm, g_h[1] + s * 256, HD,
                          wgW(pr, g) + (size_t)(PD + c0) * HD + s * 256,
                          HD, 8, acc);
                store_part(g_pwg[g][s], PD, c0, acc);
            }
        }
    }
    gridbar();

    // ---- PF2: final out-combine (16) + m1-combine (8) ----
    for (int tile = blockIdx.x; tile < 24; tile += NBLK) {
        if (tile < 16) ec_out(TSTEPS - 1, tile, pr);
        else           ec_m(1, tile - 16, pr, dopa, sero);
    }
    gridbar();

    // ---- PF3: h_final, m_final (guarded by out_size) ----
    {
        long long base_h = (long long)BB * TSTEPS * OD;
        long long base_m = base_h + (long long)LNUM * BB * HD;
        const float* hp = &g_h[0][0];
        for (int i = blockIdx.x * NTHR + tid; i < LNUM * BB * HD; i += NBLK * NTHR)
            if (base_h + i < pr.out_size) pr.out[base_h + i] = hp[i];
        const float* mp = &g_m[0][0];
        for (int i = blockIdx.x * NTHR + tid; i < LNUM * BB * PD; i += NBLK * NTHR)
            if (base_m + i < pr.out_size) pr.out[base_m + i] = mp[i];
    }
}

extern "C" void kernel_launch(void* const* d_in, const int* in_sizes, int n_in,
                              void* d_out, int out_size) {
    Params p;
    p.x    = (const float*)d_in[0];
    p.Wr   = (const float*)d_in[1];
    p.br   = (const float*)d_in[2];
    p.Wu   = (const float*)d_in[3];
    p.bu   = (const float*)d_in[4];
    p.Wn   = (const float*)d_in[5];
    p.bn   = (const float*)d_in[6];
    p.Wmr  = (const float*)d_in[7];
    p.bmr  = (const float*)d_in[8];
    p.Wmw  = (const float*)d_in[9];
    p.bmw  = (const float*)d_in[10];
    p.Wmu  = (const float*)d_in[11];
    p.bmu  = (const float*)d_in[12];
    p.Wmh  = (const float*)d_in[13];
    p.bmh  = (const float*)d_in[14];
    p.Wd   = (const float*)d_in[15];
    p.bd   = (const float*)d_in[16];
    p.Ws   = (const float*)d_in[17];
    p.bs   = (const float*)d_in[18];
    p.Wout = (const float*)d_in[19];
    p.bout = (const float*)d_in[20];
    p.dop  = (const float*)d_in[21];
    p.ser  = (const float*)d_in[22];
    p.out  = (float*)d_out;
    p.out_size = (long long)out_size;
    gru_kernel<<<NBLK, NTHR>>>(p);
}

// round 11
// speedup vs baseline: 1.4644x; 1.0087x over previous
#include <cuda_runtime.h>
#include <cuda_bf16.h>

#define LNUM 2
#define BB 64
#define TSTEPS 512
#define DIN 512
#define HD 512
#define PD 256
#define OD 512
#define NBLK 148
#define NTHR 256

// ----------------- persistent device state (no allocations) -----------------
__device__ float g_h[LNUM][BB * HD];    // h_mem per layer
__device__ float g_m[LNUM][BB * PD];    // memory per layer
__device__ float g_rh[BB * HD];         // sigma(r) * h_old   (current layer)
__device__ float g_us[BB * HD];         // sigma(u)           (current layer)
__device__ float g_hc[BB * HD];         // h_cand             (current layer)
__device__ float g_mo[BB * PD];         // read_gate * m      (current layer)
__device__ float g_pr[4][BB * HD];      // r preact partials (split-4)
__device__ float g_pu[4][BB * HD];      // u preact partials (split-4)
__device__ float g_pn[4][BB * HD];      // n preact partials (2 x-half + 2 rh-half)
__device__ float g_pwg[4][2][BB * PD];  // write-gate raw partials: mw,mu,d,s x split-2
__device__ float g_po[2][BB * OD];      // output raw partials (split-2)
__device__ unsigned g_count;
__device__ unsigned g_gen;

struct Params {
    const float *x, *Wr, *br, *Wu, *bu, *Wn, *bn, *Wmr, *bmr, *Wmw, *bmw,
                *Wmu, *bmu, *Wmh, *bmh, *Wd, *bd, *Ws, *bs, *Wout, *bout,
                *dop, *ser;
    float* out;
    long long out_size;
};

__device__ __forceinline__ float sigf(float v) { return 1.f / (1.f + __expf(-v)); }
__device__ __forceinline__ float tanhf_(float v) {
    float e = __expf(-2.f * fabsf(v));
    float r = (1.f - e) / (1.f + e);
    return v < 0.f ? -r : r;
}

__device__ __forceinline__ void gridbar() {
    __syncthreads();
    if (threadIdx.x == 0) {
        __threadfence();
        unsigned gen = *(volatile unsigned*)&g_gen;
        unsigned a = atomicAdd(&g_count, 1u);
        if (a == NBLK - 1) {
            atomicExch(&g_count, 0u);
            __threadfence();
            atomicAdd(&g_gen, 1u);
        } else {
            while (*(volatile unsigned*)&g_gen == gen) __nanosleep(64);
        }
        __threadfence();
    }
    __syncthreads();
}

struct alignas(16) SM {
    float A[2][32 * 65];  // [k][row], stride 65 -> conflict-free
    float W[2][32 * 36];  // [k][col], stride 36 -> aligned 16B vector reads
};

// C[64, 32] += A[64, 32*nch] * W[32, 32*nch]^T.
// A pre-offset to its k-window (single plain array); Wp pre-offset to (c0, k0).
// Thread map: row = tid&63, colgroup = tid>>6 (8 cols/thread).
// Inner loop: packed dual-fp32 FMAs (fma.rn.f32x2 -> FFMA2), IEEE-identical
// to scalar fmaf with the same accumulation order.
__device__ __forceinline__ void gemm_tile(
    SM& sm, const float* __restrict__ A, long lda,
    const float* __restrict__ Wp, int wstr, int nch, float accf[8])
{
    const int tid = threadIdx.x;
    const int kq = tid & 31;
    const int rq = tid >> 5;   // 0..7
    const int row = tid & 63;
    const int cg = tid >> 6;   // 0..3
    float ra[8], rw[4];
    unsigned long long acc2[4] = {0ull, 0ull, 0ull, 0ull};

    // prologue: chunk 0
#pragma unroll
    for (int i = 0; i < 8; i++) ra[i] = A[(long)(rq + 8 * i) * lda + kq];
#pragma unroll
    for (int i = 0; i < 4; i++) rw[i] = Wp[(size_t)(rq + 8 * i) * wstr + kq];
#pragma unroll
    for (int i = 0; i < 8; i++) sm.A[0][kq * 65 + rq + 8 * i] = ra[i];
#pragma unroll
    for (int i = 0; i < 4; i++) sm.W[0][kq * 36 + rq + 8 * i] = rw[i];

#pragma unroll 1
    for (int ch = 0; ch < nch; ch++) {
        __syncthreads();
        const bool more = (ch + 1 < nch);
        if (more) {
            int kb = ((ch + 1) << 5) + kq;
#pragma unroll
            for (int i = 0; i < 8; i++) ra[i] = A[(long)(rq + 8 * i) * lda + kb];
#pragma unroll
            for (int i = 0; i < 4; i++) rw[i] = Wp[(size_t)(rq + 8 * i) * wstr + kb];
        }
        const int b = ch & 1;
        const float* as = &sm.A[b][row];
        const float* ws = &sm.W[b][cg * 8];
#pragma unroll
        for (int k = 0; k < 32; k++) {
            float a = as[k * 65];
            unsigned long long aa;
            asm("mov.b64 %0, {%1, %1};" : "=l"(aa) : "f"(a));
            ulonglong2 w01 = *(const ulonglong2*)(ws + k * 36);
            ulonglong2 w23 = *(const ulonglong2*)(ws + k * 36 + 4);
            asm("fma.rn.f32x2 %0, %1, %2, %0;" : "+l"(acc2[0]) : "l"(aa), "l"(w01.x));
            asm("fma.rn.f32x2 %0, %1, %2, %0;" : "+l"(acc2[1]) : "l"(aa), "l"(w01.y));
            asm("fma.rn.f32x2 %0, %1, %2, %0;" : "+l"(acc2[2]) : "l"(aa), "l"(w23.x));
            asm("fma.rn.f32x2 %0, %1, %2, %0;" : "+l"(acc2[3]) : "l"(aa), "l"(w23.y));
        }
        if (more) {
            const int nb = (ch + 1) & 1;
#pragma unroll
            for (int i = 0; i < 8; i++) sm.A[nb][kq * 65 + rq + 8 * i] = ra[i];
#pragma unroll
            for (int i = 0; i < 4; i++) sm.W[nb][kq * 36 + rq + 8 * i] = rw[i];
        }
    }
    __syncthreads();
#pragma unroll
    for (int j = 0; j < 4; j++)
        asm("mov.b64 {%0, %1}, %2;"
            : "=f"(accf[2 * j]), "=f"(accf[2 * j + 1]) : "l"(acc2[j]));
}

__device__ __forceinline__ void store_part(float* __restrict__ part, int N,
                                           int c0, const float* accf) {
    const int row = threadIdx.x & 63, cg = threadIdx.x >> 6;
    float4* p = (float4*)(part + (size_t)row * N + c0 + cg * 8);
    p[0] = make_float4(accf[0], accf[1], accf[2], accf[3]);
    p[1] = make_float4(accf[4], accf[5], accf[6], accf[7]);
}

__device__ __forceinline__ const float* wgW(const Params& pr, int g) {
    return (g == 0) ? pr.Wmw : (g == 1) ? pr.Wmu : (g == 2) ? pr.Wd : pr.Ws;
}

// elementwise: materialize sigma(r)*h and sigma(u) from split-4 partials
__device__ __forceinline__ void ew_ru(int l, int e, const Params& pr) {
    const int tid = threadIdx.x;
#pragma unroll
    for (int j = 0; j < 8; j++) {
        int i = e * 2048 + j * 256 + tid;
        int c = i & 511;
        float rr = g_pr[0][i] + g_pr[1][i] + g_pr[2][i] + g_pr[3][i]
                   + pr.br[l * HD + c];
        g_rh[i] = sigf(rr) * g_h[l][i];
        float uu = g_pu[0][i] + g_pu[1][i] + g_pu[2][i] + g_pu[3][i]
                   + pr.bu[l * HD + c];
        g_us[i] = sigf(uu);
    }
}

// elementwise: materialize h_cand from n partials + sigma(u)
__device__ __forceinline__ void ew_hc(int l, int e, const Params& pr) {
    const int tid = threadIdx.x;
#pragma unroll
    for (int j = 0; j < 8; j++) {
        int i = e * 2048 + j * 256 + tid;
        int c = i & 511;
        float nn = g_pn[0][i] + g_pn[1][i] + g_pn[2][i] + g_pn[3][i]
                   + pr.bn[l * HD + c];
        float u = g_us[i];
        g_hc[i] = (1.f - u) * g_h[l][i] + u * tanhf_(nn);
    }
}

// elementwise: apply memory update for layer l from raw write-gate partials
__device__ __forceinline__ void ec_m(int l, int e, const Params& pr,
                                     float dopa, float sero) {
    const int tid = threadIdx.x;
#pragma unroll
    for (int j = 0; j < 8; j++) {
        int i = e * 2048 + j * 256 + tid;
        int c = i & 255;
        float wmw = g_pwg[0][0][i] + g_pwg[0][1][i] + pr.bmw[l * PD + c];
        float wmu = g_pwg[1][0][i] + g_pwg[1][1][i] + pr.bmu[l * PD + c];
        float wd  = g_pwg[2][0][i] + g_pwg[2][1][i] + pr.bd[l * PD + c];
        float wsv = g_pwg[3][0][i] + g_pwg[3][1][i] + pr.bs[l * PD + c];
        float w = sigf(wmw) * sigf(wd * dopa) * (1.f - sigf(wsv * sero));
        g_m[l][i] = (1.f - w) * g_m[l][i] + w * tanhf_(wmu);
    }
}

__device__ __forceinline__ void ec_out(int tprev, int e, const Params& pr) {
    const int tid = threadIdx.x;
#pragma unroll
    for (int j = 0; j < 8; j++) {
        int i = e * 2048 + j * 256 + tid;
        int r = i >> 9, c = i & 511;
        pr.out[((size_t)r * TSTEPS + tprev) * OD + c] =
            g_po[0][i] + g_po[1][i] + pr.bout[c];
    }
}

__global__ void __launch_bounds__(NTHR, 1)
gru_kernel(Params pr)
{
    __shared__ SM sm;
    const int tid = threadIdx.x;
    const int row = tid & 63;
    const int cg = tid >> 6;
    const float dopa = pr.dop[0];
    const float sero = pr.ser[0];

    for (int i = blockIdx.x * NTHR + tid; i < LNUM * BB * HD; i += NBLK * NTHR)
        (&g_h[0][0])[i] = 0.f;
    for (int i = blockIdx.x * NTHR + tid; i < LNUM * BB * PD; i += NBLK * NTHR)
        (&g_m[0][0])[i] = 0.f;
    gridbar();

    const long LDX = (long)TSTEPS * DIN;  // batch-row stride of x

    for (int t = 0; t < TSTEPS; t++) {
        const float* xt = pr.x + (size_t)t * DIN;
        float acc[8];

        for (int l = 0; l < LNUM; l++) {
            // ---- A: r,u split-4 (128 tiles, 8 chunks each) ----
            for (int tile = blockIdx.x; tile < 128; tile += NBLK) {
                int which = tile >> 6, q = tile & 63;
                int c0 = (q >> 2) * 32, s = q & 3, k0 = s * 256;
                const float* A; long lda;
                if (l == 0) {
                    if (s < 2) { A = xt + k0; lda = LDX; }
                    else       { A = g_h[0] + (k0 - 512); lda = HD; }
                } else {
                    if (s < 2) { A = g_h[0] + k0; lda = HD; }
                    else       { A = g_h[1] + (k0 - 512); lda = HD; }
                }
                const float* W = (which ? pr.Wu : pr.Wr)
                                 + (size_t)(l * HD + c0) * (DIN + HD) + k0;
                gemm_tile(sm, A, lda, W, DIN + HD, 8, acc);
                store_part((which ? g_pu : g_pr)[s], HD, c0, acc);
            }
            gridbar();

            // ---- B: ew_ru (16) + n-firsthalf split-2 (32)
            //         + [l==0,t>0: out(t-1) split-2 (32)]
            //         + [wg of other layer, split-2 (64)] ----
            {
                int ntB = (l == 0) ? (t ? 144 : 48) : 112;
                int wgbase = (l == 0) ? 80 : 48;
                for (int tile = blockIdx.x; tile < ntB; tile += NBLK) {
                    if (tile < 16) {
                        ew_ru(l, tile, pr);
                    } else if (tile < 48) {  // n first half (x-part / h0-part)
                        int q = tile - 16;
                        int c0 = (q >> 1) * 32, s = q & 1, k0 = s * 256;
                        const float* A; long lda;
                        if (l == 0) { A = xt + k0; lda = LDX; }
                        else        { A = g_h[0] + k0; lda = HD; }
                        const float* W = pr.Wn
                            + (size_t)(l * HD + c0) * (DIN + HD) + k0;
                        gemm_tile(sm, A, lda, W, DIN + HD, 8, acc);
                        store_part(g_pn[s], HD, c0, acc);
                    } else if (l == 0 && tile < 80) {  // out(t-1) from h1(t-1)
                        int q = tile - 48;
                        int c0 = (q >> 1) * 32, s = q & 1;
                        gemm_tile(sm, g_h[1] + s * 256, HD,
                                  pr.Wout + (size_t)c0 * HD + s * 256, HD, 8,
                                  acc);
                        store_part(g_po[s], OD, c0, acc);
                    } else {  // write gates of layer lw
                        int lw = 1 - l;  // l==0: layer-1 gates (t-1); l==1: layer-0 gates (t)
                        int q = tile - wgbase, g = q >> 4, r2 = q & 15;
                        int c0 = (r2 >> 1) * 32, s = r2 & 1;
                        gemm_tile(sm, g_h[lw] + s * 256, HD,
                                  wgW(pr, g) + (size_t)(lw * PD + c0) * HD
                                      + s * 256,
                                  HD, 8, acc);
                        store_part(g_pwg[g][s], PD, c0, acc);
                    }
                }
            }
            gridbar();

            // ---- C: n-secondhalf split-2 (32)
            //         + [l==0,t>0: ec_m(1) (8) + ec_out(t-1) (16)]
            //         + [l==1: ec_m(0) (8)] ----
            {
                int ntC = (l == 0) ? (t ? 56 : 32) : 40;
                for (int tile = blockIdx.x; tile < ntC; tile += NBLK) {
                    if (tile < 32) {
                        int c0 = (tile >> 1) * 32, s = tile & 1, k0 = s * 256;
                        const float* W = pr.Wn
                            + (size_t)(l * HD + c0) * (DIN + HD) + DIN + k0;
                        gemm_tile(sm, g_rh + k0, HD, W, DIN + HD, 8, acc);
                        store_part(g_pn[2 + s], HD, c0, acc);
                    } else if (tile < 40) {
                        ec_m(1 - l, tile - 32, pr, dopa, sero);
                    } else {
                        ec_out(t - 1, tile - 40, pr);
                    }
                }
            }
            gridbar();

            // ---- D: materialize h_cand (16 tiles) ----
            for (int tile = blockIdx.x; tile < 16; tile += NBLK)
                ew_hc(l, tile, pr);
            gridbar();

            // ---- E: read gate, K=512 unsplit (8 tiles, 16 chunks) ----
            for (int tile = blockIdx.x; tile < 8; tile += NBLK) {
                int c0 = tile * 32;
                gemm_tile(sm, g_hc, HD,
                          pr.Wmr + (size_t)(l * PD + c0) * HD, HD, 16, acc);
#pragma unroll
                for (int j = 0; j < 8; j++) {
                    int c = c0 + cg * 8 + j;
                    int idx = row * PD + c;
                    g_mo[idx] = sigf(acc[j] + pr.bmr[l * PD + c]) * g_m[l][idx];
                }
            }
            gridbar();

            // ---- F: h_mem = hc + mo*Wmh^T + bmh, K=256 (16 tiles, 8 chunks) ----
            for (int tile = blockIdx.x; tile < 16; tile += NBLK) {
                int c0 = tile * 32;
                gemm_tile(sm, g_mo, PD,
                          pr.Wmh + (size_t)(l * HD + c0) * PD, PD, 8, acc);
#pragma unroll
                for (int j = 0; j < 8; j++) {
                    int c = c0 + cg * 8 + j;
                    int idx = row * HD + c;
                    g_h[l][idx] = g_hc[idx] + acc[j] + pr.bmh[l * HD + c];
                }
            }
            gridbar();
        }
    }

    // ---- PF1: out(T-1) split-2 (32) + layer-1 write gates split-2 (64) ----
    {
        float acc[8];
        for (int tile = blockIdx.x; tile < 96; tile += NBLK) {
            if (tile < 32) {
                int c0 = (tile >> 1) * 32, s = tile & 1;
                gemm_tile(sm, g_h[1] + s * 256, HD,
                          pr.Wout + (size_t)c0 * HD + s * 256, HD, 8, acc);
                store_part(g_po[s], OD, c0, acc);
            } else {
                int q = tile - 32, g = q >> 4, r2 = q & 15;
                int c0 = (r2 >> 1) * 32, s = r2 & 1;
                gemm_tile(sm, g_h[1] + s * 256, HD,
                          wgW(pr, g) + (size_t)(PD + c0) * HD + s * 256,
                          HD, 8, acc);
                store_part(g_pwg[g][s], PD, c0, acc);
            }
        }
    }
    gridbar();

    // ---- PF2: final out-combine (16) + m1-combine (8) ----
    for (int tile = blockIdx.x; tile < 24; tile += NBLK) {
        if (tile < 16) ec_out(TSTEPS - 1, tile, pr);
        else           ec_m(1, tile - 16, pr, dopa, sero);
    }
    gridbar();

    // ---- PF3: h_final, m_final (guarded by out_size) ----
    {
        long long base_h = (long long)BB * TSTEPS * OD;
        long long base_m = base_h + (long long)LNUM * BB * HD;
        const float* hp = &g_h[0][0];
        for (int i = blockIdx.x * NTHR + tid; i < LNUM * BB * HD; i += NBLK * NTHR)
            if (base_h + i < pr.out_size) pr.out[base_h + i] = hp[i];
        const float* mp = &g_m[0][0];
        for (int i = blockIdx.x * NTHR + tid; i < LNUM * BB * PD; i += NBLK * NTHR)
            if (base_m + i < pr.out_size) pr.out[base_m + i] = mp[i];
    }
}

extern "C" void kernel_launch(void* const* d_in, const int* in_sizes, int n_in,
                              void* d_out, int out_size) {
    Params p;
    p.x    = (const float*)d_in[0];
    p.Wr   = (const float*)d_in[1];
    p.br   = (const float*)d_in[2];
    p.Wu   = (const float*)d_in[3];
    p.bu   = (const float*)d_in[4];
    p.Wn   = (const float*)d_in[5];
    p.bn   = (const float*)d_in[6];
    p.Wmr  = (const float*)d_in[7];
    p.bmr  = (const float*)d_in[8];
    p.Wmw  = (const float*)d_in[9];
    p.bmw  = (const float*)d_in[10];
    p.Wmu  = (const float*)d_in[11];
    p.bmu  = (const float*)d_in[12];
    p.Wmh  = (const float*)d_in[13];
    p.bmh  = (const float*)d_in[14];
    p.Wd   = (const float*)d_in[15];
    p.bd   = (const float*)d_in[16];
    p.Ws   = (const float*)d_in[17];
    p.bs   = (const float*)d_in[18];
    p.Wout = (const float*)d_in[19];
    p.bout = (const float*)d_in[20];
    p.dop  = (const float*)d_in[21];
    p.ser  = (const float*)d_in[22];
    p.out  = (float*)d_out;
    p.out_size = (long long)out_size;
    gru_kernel<<<NBLK, NTHR>>>(p);
}